// round 5
// baseline (speedup 1.0000x reference)
#include <cuda_runtime.h>
#include <cstdint>

#define HH 1536
#define WW 2048
#define NN (HH*WW)
#define TILES_X (WW/32)
#define TILES_Y (HH/32)
#define NTILES (TILES_X*TILES_Y)
#define MAXR (NTILES*256)          // safe upper bound on tile-local labels

// scratch (device globals: allocation-free rule)
__device__ int g_parent[NN];       // union-find parent (global root idx per pixel); -1 = background
__device__ int g_xmin[NN];         // only root slots populated
__device__ int g_xmax[NN];
__device__ int g_ymax[NN];
__device__ int g_tflag[NN];
__device__ int g_roots[MAXR];
__device__ int g_nroots;

// ---------------- smem union-find helpers ----------------
__device__ __forceinline__ int sfind(volatile int* L, int i) {
    int n;
    while ((n = L[i]) != i) i = n;
    return i;
}
__device__ __forceinline__ void sunite(int* L, int a, int b) {
    volatile int* V = L;
    while (true) {
        a = sfind(V, a);
        b = sfind(V, b);
        if (a == b) return;
        int lo = min(a, b), hi = max(a, b);
        int old = atomicMin(&L[hi], lo);
        if (old == hi) return;
        a = lo; b = old;
    }
}

// ---------------- global union-find (links point to smaller index) ----------------
__device__ __forceinline__ int uf_find(int i) {
    int n;
    while ((n = __ldcg(&g_parent[i])) != i) i = n;
    return i;
}
__device__ __forceinline__ void uf_union(int a, int b) {
    while (true) {
        a = uf_find(a);
        b = uf_find(b);
        if (a == b) return;
        int lo = min(a, b), hi = max(a, b);
        int old = atomicMin(&g_parent[hi], lo);
        if (old == hi) return;
        a = lo; b = old;
    }
}

// ---------------- reset ----------------
__global__ void k_reset() { g_nroots = 0; }

// ---------------- fused: threshold + dilate + tile CCL + per-label bbox ----------------
__global__ void __launch_bounds__(1024, 1) k_tile(const float* __restrict__ x) {
    __shared__ unsigned char cmb[34][36];            // comb mask with 1-halo, padded
    __shared__ unsigned char fgm[32][33];            // dilated fg
    __shared__ int lab[1024];
    __shared__ int sxmin[1024], sxmax[1024], symax[1024], stext[1024];

    int tx = threadIdx.x, ty = threadIdx.y;
    int lid = ty * 32 + tx;
    int bx = blockIdx.x * 32, by = blockIdx.y * 32;

    // halo load of comb mask, computed straight from x
    for (int k = lid; k < 34 * 34; k += 1024) {
        int ly = k / 34, lx = k % 34;
        int gy = by + ly - 1, gx = bx + lx - 1;
        unsigned char v = 0;
        if ((unsigned)gy < HH && (unsigned)gx < WW) {
            float2 p = ((const float2*)x)[gy * WW + gx];
            v = (unsigned char)((p.x > 0.4f) | (p.y > 0.4f));
        }
        cmb[ly][lx] = v;
    }
    // own text bit
    float2 own = ((const float2*)x)[(by + ty) * WW + (bx + tx)];
    int text = own.x > 0.4f;
    __syncthreads();

    // 3x3 dilation
    int fg = 0;
#pragma unroll
    for (int dy = 0; dy < 3; dy++)
#pragma unroll
        for (int dx = 0; dx < 3; dx++)
            fg |= cmb[ty + dy][tx + dx];
    fgm[ty][tx] = (unsigned char)fg;
    lab[lid] = lid;
    sxmin[lid] = 1 << 30; sxmax[lid] = -1; symax[lid] = -1; stext[lid] = 0;
    __syncthreads();

    // in-tile union-find: union with left and up neighbors
    if (fg) {
        if (tx > 0 && fgm[ty][tx - 1]) sunite(lab, lid, lid - 1);
        if (ty > 0 && fgm[ty - 1][tx]) sunite(lab, lid, lid - 32);
    }
    __syncthreads();

    int rt = -1;
    if (fg) {
        rt = sfind(lab, lid);
        lab[lid] = rt;   // compress (monotone, root-preserving: safe concurrently)
    }

    // warp-aggregated per-label reduction, leaders do smem atomics
    unsigned peers = __match_any_sync(0xffffffffu, rt);
    int cmin = __reduce_min_sync(peers, fg ? tx : (1 << 30));
    int cmax = __reduce_max_sync(peers, fg ? tx : -1);
    int rmax = __reduce_max_sync(peers, fg ? ty : -1);
    unsigned tor = __reduce_or_sync(peers, fg ? (unsigned)text : 0u);
    int lane = tx;  // threadIdx.x is lane for 32-wide rows
    if (fg && lane == (__ffs(peers) - 1)) {
        atomicMin(&sxmin[rt], cmin);
        atomicMax(&sxmax[rt], cmax);
        atomicMax(&symax[rt], rmax);
        if (tor) stext[rt] = 1;            // idempotent
    }
    __syncthreads();

    // write parent for every pixel (1-hop to tile root); roots publish partial bbox
    int gi = (by + ty) * WW + (bx + tx);
    int rootg = -1;
    if (fg) rootg = (by + (rt >> 5)) * WW + (bx + (rt & 31));
    g_parent[gi] = rootg;
    if (fg && rt == lid) {
        g_xmin[gi] = bx + sxmin[lid];
        g_xmax[gi] = bx + sxmax[lid];
        g_ymax[gi] = by + symax[lid];
        g_tflag[gi] = stext[lid];
        int slot = atomicAdd(&g_nroots, 1);
        g_roots[slot] = gi;
    }
}

// ---------------- cross-tile merge: boundary pixel pairs only ----------------
#define NVB (63 * HH)      // vertical internal boundaries
#define NHB (47 * WW)      // horizontal internal boundaries
__global__ void k_merge() {
    int i = blockIdx.x * blockDim.x + threadIdx.x;
    int a, c;
    if (i < NVB) {
        int b = i / HH, y = i % HH;
        a = y * WW + (b * 32 + 31);
        c = a + 1;
    } else if (i < NVB + NHB) {
        int j = i - NVB;
        int b = j / WW, xx = j % WW;
        a = (b * 32 + 31) * WW + xx;
        c = a + WW;
    } else return;
    int pa = __ldcg(&g_parent[a]); if (pa < 0) return;
    int pc = __ldcg(&g_parent[c]); if (pc < 0) return;
    if (pa == pc) return;
    uf_union(pa, pc);
}

// ---------------- fold tile-partial bboxes into final roots ----------------
__global__ void k_push() {
    int j = blockIdx.x * blockDim.x + threadIdx.x;
    if (j >= g_nroots) return;
    int r = g_roots[j];
    int f = uf_find(r);
    if (f == r) return;
    atomicMin(&g_xmin[f], g_xmin[r]);
    atomicMax(&g_xmax[f], g_xmax[r]);
    atomicMax(&g_ymax[f], g_ymax[r]);
    if (g_tflag[r]) atomicMax(&g_tflag[f], 1);
}

// ---------------- output (float32) ----------------
__global__ void k_zero4(float* __restrict__ out, int n4) {
    int i = blockIdx.x * blockDim.x + threadIdx.x;
    if (i < n4) ((float4*)out)[i] = make_float4(0.f, 0.f, 0.f, 0.f);
}
__global__ void k_zero1(float* __restrict__ out, int base, int n) {
    int i = blockIdx.x * blockDim.x + threadIdx.x;
    if (i < n) out[base + i] = 0.f;
}

__global__ void k_out(float* __restrict__ out) {
    int j = blockIdx.x * blockDim.x + threadIdx.x;
    if (j >= g_nroots) return;
    int r = g_roots[j];
    if (__ldcg(&g_parent[r]) != r) return;   // final root only
    int ymin = r / WW;                        // root = min flat index
    int xmin = g_xmin[r];
    int h = g_ymax[r] - ymin;
    int w = g_xmax[r] - xmin;
    if (h > 4 && w > 4 && g_tflag[r]) {
        ((float4*)out)[r] = make_float4((float)ymin, (float)xmin, (float)h, (float)w);
        out[4 * NN + r] = 1.0f;
    }
}

extern "C" void kernel_launch(void* const* d_in, const int* in_sizes, int n_in,
                              void* d_out, int out_size) {
    const float* x = (const float*)d_in[0];
    float* out = (float*)d_out;

    k_reset<<<1, 1>>>();

    dim3 bt(32, 32), gt(TILES_X, TILES_Y);
    k_tile<<<gt, bt>>>(x);

    k_merge<<<(NVB + NHB + 255) / 256, 256>>>();

    k_push<<<MAXR / 256, 256>>>();

    int n4 = out_size / 4;
    if (n4 > 0) k_zero4<<<(n4 + 255) / 256, 256>>>(out, n4);
    int rem = out_size - n4 * 4;
    if (rem > 0) k_zero1<<<1, 256>>>(out, n4 * 4, rem);

    k_out<<<MAXR / 256, 256>>>(out);
}

// round 7
// speedup vs baseline: 1.0045x; 1.0045x over previous
#include <cuda_runtime.h>
#include <cstdint>

#define HH 1536
#define WW 2048
#define NN (HH*WW)
#define TILES_X (WW/32)
#define TILES_Y (HH/32)
#define NTILES (TILES_X*TILES_Y)
#define MAXR (NTILES*256)          // safe upper bound on tile-local labels

// scratch (device globals: allocation-free rule)
__device__ int g_parent[NN];       // union-find parent; -1 = background
__device__ int g_xmin[NN];         // only root slots populated
__device__ int g_xmax[NN];
__device__ int g_ymax[NN];
__device__ int g_tflag[NN];
__device__ int g_roots[MAXR];
__device__ int g_nroots;

// ---------------- smem union-find helpers ----------------
__device__ __forceinline__ int sfind(volatile int* L, int i) {
    int n;
    while ((n = L[i]) != i) i = n;
    return i;
}
__device__ __forceinline__ void sunite(int* L, int a, int b) {
    volatile int* V = L;
    while (true) {
        a = sfind(V, a);
        b = sfind(V, b);
        if (a == b) return;
        int lo = min(a, b), hi = max(a, b);
        int old = atomicMin(&L[hi], lo);
        if (old == hi) return;
        a = lo; b = old;
    }
}

// ---------------- global union-find (links point to smaller index) ----------------
// find WITHOUT compression: used during k_merge (stores would race with atomicMin unions)
__device__ __forceinline__ int uf_find(int i) {
    int n;
    while ((n = __ldcg(&g_parent[i])) != i) i = n;
    return i;
}
__device__ __forceinline__ void uf_union(int a, int b) {
    while (true) {
        a = uf_find(a);
        b = uf_find(b);
        if (a == b) return;
        int lo = min(a, b), hi = max(a, b);
        int old = atomicMin(&g_parent[hi], lo);
        if (old == hi) return;
        a = lo; b = old;
    }
}
// find WITH path halving: safe once all unions are done (stores only write
// ancestors; the root's own slot is never modified)
__device__ __forceinline__ int uf_find_halve(int i) {
    int n = __ldcg(&g_parent[i]);
    while (n != i) {
        int g = __ldcg(&g_parent[n]);
        if (g != n) g_parent[i] = g;   // halve
        i = n; n = g;
    }
    return i;
}

// ---------------- reset ----------------
__global__ void k_reset() { g_nroots = 0; }

// ---------------- fused: threshold + dilate + tile CCL + per-label bbox ----------------
__global__ void __launch_bounds__(1024, 1) k_tile(const float* __restrict__ x) {
    __shared__ unsigned char cmb[34][36];            // comb mask with 1-halo, padded
    __shared__ unsigned char fgm[32][33];            // dilated fg
    __shared__ int lab[1024];
    __shared__ int sxmin[1024], sxmax[1024], symax[1024], stext[1024];

    int tx = threadIdx.x, ty = threadIdx.y;
    int lid = ty * 32 + tx;
    int bx = blockIdx.x * 32, by = blockIdx.y * 32;

    // halo load of comb mask, computed straight from x
    for (int k = lid; k < 34 * 34; k += 1024) {
        int ly = k / 34, lx = k % 34;
        int gy = by + ly - 1, gx = bx + lx - 1;
        unsigned char v = 0;
        if ((unsigned)gy < HH && (unsigned)gx < WW) {
            float2 p = ((const float2*)x)[gy * WW + gx];
            v = (unsigned char)((p.x > 0.4f) | (p.y > 0.4f));
        }
        cmb[ly][lx] = v;
    }
    // own text bit
    float2 own = ((const float2*)x)[(by + ty) * WW + (bx + tx)];
    int text = own.x > 0.4f;
    __syncthreads();

    // 3x3 dilation
    int fg = 0;
#pragma unroll
    for (int dy = 0; dy < 3; dy++)
#pragma unroll
        for (int dx = 0; dx < 3; dx++)
            fg |= cmb[ty + dy][tx + dx];
    fgm[ty][tx] = (unsigned char)fg;
    lab[lid] = lid;
    sxmin[lid] = 1 << 30; sxmax[lid] = -1; symax[lid] = -1; stext[lid] = 0;
    __syncthreads();

    // in-tile union-find: union with left and up neighbors
    if (fg) {
        if (tx > 0 && fgm[ty][tx - 1]) sunite(lab, lid, lid - 1);
        if (ty > 0 && fgm[ty - 1][tx]) sunite(lab, lid, lid - 32);
    }
    __syncthreads();

    int rt = -1;
    if (fg) rt = sfind(lab, lid);

    // warp-aggregated per-label reduction, leaders do smem atomics
    unsigned peers = __match_any_sync(0xffffffffu, rt);
    int cmin = __reduce_min_sync(peers, fg ? tx : (1 << 30));
    int cmax = __reduce_max_sync(peers, fg ? tx : -1);
    int rmax = __reduce_max_sync(peers, fg ? ty : -1);
    unsigned tor = __reduce_or_sync(peers, fg ? (unsigned)text : 0u);
    if (fg && tx == (__ffs(peers) - 1 + (ty * 32) - lid + tx)) { /* leader check below */ }
    if (fg && (lid & 31) == (__ffs(peers) - 1)) {
        atomicMin(&sxmin[rt], cmin);
        atomicMax(&sxmax[rt], cmax);
        atomicMax(&symax[rt], rmax);
        if (tor) stext[rt] = 1;            // idempotent
    }
    __syncthreads();

    // write parent for every pixel (1-hop to tile root); roots publish partial bbox
    int gi = (by + ty) * WW + (bx + tx);
    int rootg = -1;
    if (fg) rootg = (by + (rt >> 5)) * WW + (bx + (rt & 31));
    g_parent[gi] = rootg;
    if (fg && rt == lid) {
        g_xmin[gi] = bx + sxmin[lid];
        g_xmax[gi] = bx + sxmax[lid];
        g_ymax[gi] = by + symax[lid];
        g_tflag[gi] = stext[lid];
        int slot = atomicAdd(&g_nroots, 1);
        g_roots[slot] = gi;
    }
}

// ---------------- cross-tile merge: boundary pairs, warp-deduped ----------------
#define NVB (63 * HH)      // vertical internal boundaries
#define NHB (47 * WW)      // horizontal internal boundaries
__global__ void k_merge() {
    int i = blockIdx.x * blockDim.x + threadIdx.x;
    int a = 0, c = 0;
    bool inr = false;
    if (i < NVB) {
        int b = i / HH, y = i % HH;
        a = y * WW + (b * 32 + 31);
        c = a + 1;
        inr = true;
    } else if (i < NVB + NHB) {
        int j = i - NVB;
        int b = j / WW, xx = j % WW;
        a = (b * 32 + 31) * WW + xx;
        c = a + WW;
        inr = true;
    }
    int pa = -1, pc = -1;
    if (inr) {
        pa = __ldcg(&g_parent[a]);
        pc = __ldcg(&g_parent[c]);
    }
    bool val = inr && pa >= 0 && pc >= 0 && pa != pc;
    // dedupe identical (pa,pc) pairs within the warp: adjacent boundary pixels
    // almost always share the same tile-root pair
    unsigned long long key = val ? ((((unsigned long long)(unsigned)pa) << 32) | (unsigned)pc)
                                 : ~0ull;
    unsigned grp = __match_any_sync(0xffffffffu, key);
    if (val && (threadIdx.x & 31) == (unsigned)(__ffs(grp) - 1))
        uf_union(pa, pc);
}

// ---------------- fold tile-partial bboxes into final roots (path-halving finds) ----------------
__global__ void k_push() {
    int nr = g_nroots;
    for (int j = blockIdx.x * blockDim.x + threadIdx.x; j < nr;
         j += gridDim.x * blockDim.x) {
        int r = g_roots[j];
        int f = uf_find_halve(r);
        if (f == r) continue;
        atomicMin(&g_xmin[f], g_xmin[r]);
        atomicMax(&g_xmax[f], g_xmax[r]);
        atomicMax(&g_ymax[f], g_ymax[r]);
        if (g_tflag[r]) atomicMax(&g_tflag[f], 1);
    }
}

// ---------------- output (float32) ----------------
__global__ void k_zero4(float* __restrict__ out, int n4) {
    int i = blockIdx.x * blockDim.x + threadIdx.x;
    if (i < n4) ((float4*)out)[i] = make_float4(0.f, 0.f, 0.f, 0.f);
}
__global__ void k_zero1(float* __restrict__ out, int base, int n) {
    int i = blockIdx.x * blockDim.x + threadIdx.x;
    if (i < n) out[base + i] = 0.f;
}

__global__ void k_out(float* __restrict__ out) {
    int nr = g_nroots;
    for (int j = blockIdx.x * blockDim.x + threadIdx.x; j < nr;
         j += gridDim.x * blockDim.x) {
        int r = g_roots[j];
        if (__ldcg(&g_parent[r]) != r) continue;   // final root only
        int ymin = r / WW;                          // root = min flat index
        int xmin = g_xmin[r];
        int h = g_ymax[r] - ymin;
        int w = g_xmax[r] - xmin;
        if (h > 4 && w > 4 && g_tflag[r]) {
            ((float4*)out)[r] = make_float4((float)ymin, (float)xmin, (float)h, (float)w);
            out[4 * NN + r] = 1.0f;
        }
    }
}

extern "C" void kernel_launch(void* const* d_in, const int* in_sizes, int n_in,
                              void* d_out, int out_size) {
    const float* x = (const float*)d_in[0];
    float* out = (float*)d_out;

    k_reset<<<1, 1>>>();

    dim3 bt(32, 32), gt(TILES_X, TILES_Y);
    k_tile<<<gt, bt>>>(x);

    k_merge<<<(NVB + NHB + 255) / 256, 256>>>();

    k_push<<<64, 256>>>();

    int n4 = out_size / 4;
    if (n4 > 0) k_zero4<<<(n4 + 255) / 256, 256>>>(out, n4);
    int rem = out_size - n4 * 4;
    if (rem > 0) k_zero1<<<1, 256>>>(out, n4 * 4, rem);

    k_out<<<64, 256>>>(out);
}

// round 8
// speedup vs baseline: 6.3213x; 6.2932x over previous
#include <cuda_runtime.h>
#include <cstdint>

#define HH 1536
#define WW 2048
#define NN (HH*WW)
#define WPR 64                 // 32-bit words per row
#define CAP 512                // max runs per row (dilated runs: period >= 5 -> <= 411)
#define NSLOT (HH*CAP)

// scratch (device globals: allocation-free rule)
__device__ uint32_t g_comb[HH * WPR];   // comb bitmap
__device__ uint32_t g_text[HH * WPR];   // text bitmap
__device__ int g_rxs[NSLOT];            // run x-start
__device__ int g_rxe[NSLOT];            // run x-end (inclusive)
__device__ int g_runcnt[HH];
__device__ int g_rpar[NSLOT];           // union-find over run slots (min-ordered)
__device__ int g_rxmin[NSLOT];
__device__ int g_rxmax[NSLOT];
__device__ int g_rymax[NSLOT];
__device__ int g_rtext[NSLOT];

// ---------------- concurrent min-union-find (all writes atomicMin) ----------------
// invariant: parent[i] <= i and parent[i] is in i's component -> find terminates,
// root of a component is its min slot; atomicMin-halving is safe concurrently
// with atomicMin unions (values only decrease, never leave the component).
__device__ __forceinline__ int uf_find(int i) {
    int n = __ldcg(&g_rpar[i]);
    while (n != i) {
        int g = __ldcg(&g_rpar[n]);
        if (g != n) atomicMin(&g_rpar[i], g);   // halve
        i = n; n = g;
    }
    return i;
}
__device__ __forceinline__ void uf_union(int a, int b) {
    while (true) {
        a = uf_find(a);
        b = uf_find(b);
        if (a == b) return;
        int lo = min(a, b), hi = max(a, b);
        int old = atomicMin(&g_rpar[hi], lo);
        if (old == hi) return;
        a = lo; b = old;
    }
}

// ---------------- pass 1: threshold -> bitmaps ----------------
__global__ void k_bits(const float* __restrict__ x) {
    int i = blockIdx.x * blockDim.x + threadIdx.x;   // pixel index; grid exact
    float2 p = ((const float2*)x)[i];
    unsigned cb = __ballot_sync(0xffffffffu, (p.x > 0.4f) | (p.y > 0.4f));
    unsigned tb = __ballot_sync(0xffffffffu, p.x > 0.4f);
    if ((threadIdx.x & 31) == 0) {
        g_comb[i >> 5] = cb;
        g_text[i >> 5] = tb;
    }
}

// ---------------- pass 2: dilate (bit-smear) + run extraction ----------------
__global__ void __launch_bounds__(256) k_runs() {
    __shared__ uint32_t sv[8][WPR + 2];   // vertical OR, 1-word sentinels
    __shared__ uint32_t sd[8][WPR];       // dilated row
    __shared__ uint32_t st[8][WPR];       // text row
    int wid = threadIdx.x >> 5, lane = threadIdx.x & 31;
    int y = blockIdx.x * 8 + wid;

    const uint32_t* rm = (y > 0) ? &g_comb[(y - 1) * WPR] : nullptr;
    const uint32_t* rc = &g_comb[y * WPR];
    const uint32_t* rp = (y < HH - 1) ? &g_comb[(y + 1) * WPR] : nullptr;

    if (lane == 0) { sv[wid][0] = 0; sv[wid][WPR + 1] = 0; }
#pragma unroll
    for (int k = 0; k < 2; k++) {
        int w = lane + k * 32;
        uint32_t v = rc[w];
        if (rm) v |= rm[w];
        if (rp) v |= rp[w];
        sv[wid][1 + w] = v;
        st[wid][w] = g_text[y * WPR + w];
    }
    __syncwarp();
#pragma unroll
    for (int k = 0; k < 2; k++) {
        int w = lane + k * 32;
        uint32_t v = sv[wid][1 + w];
        sd[wid][w] = v | (v << 1) | (v >> 1)
                   | (sv[wid][w] >> 31) | (sv[wid][2 + w] << 31);
    }
    __syncwarp();

    if (lane != 0) return;

    // serial run extraction (~2 runs/row expected)
    int cnt = 0;
    bool open = false;
    int xs = 0;
    unsigned tacc = 0;
    for (int w = 0; w <= WPR; w++) {
        unsigned b = (w < WPR) ? sd[wid][w] : 0u;
        unsigned t = (w < WPR) ? st[wid][w] : 0u;
        int pos = 0;
        while (true) {
            if (!open) {
                unsigned rem = b >> pos;            // pos in [0,31]
                if (!rem) break;
                int s = pos + __ffs(rem) - 1;
                xs = w * 32 + s; tacc = 0; open = true; pos = s;
            } else {
                unsigned rem = (~b) >> pos;
                if (!rem) {                          // run spans rest of word
                    tacc |= t & (0xffffffffu << pos);
                    break;
                }
                int e = pos + __ffs(rem) - 1;        // first clear bit, e<=31
                tacc |= t & (((1u << e) - 1) & ~((1u << pos) - 1));
                int sid = y * CAP + cnt;
                int xe = w * 32 + e - 1;
                g_rxs[sid] = xs; g_rxe[sid] = xe;
                g_rpar[sid] = sid;
                g_rxmin[sid] = xs; g_rxmax[sid] = xe;
                g_rymax[sid] = y;  g_rtext[sid] = (tacc != 0);
                cnt++;
                open = false; pos = e;
                if (pos >= 32) break;
            }
        }
    }
    g_runcnt[y] = cnt;
}

// ---------------- pass 3: link overlapping runs of adjacent rows ----------------
__global__ void k_link() {
    int y = blockIdx.x * blockDim.x + threadIdx.x;
    if (y >= HH - 1) return;
    int ca = g_runcnt[y], cb = g_runcnt[y + 1];
    int i = 0, j = 0;
    int abase = y * CAP, bbase = (y + 1) * CAP;
    while (i < ca && j < cb) {
        int axs = g_rxs[abase + i], axe = g_rxe[abase + i];
        int bxs = g_rxs[bbase + j], bxe = g_rxe[bbase + j];
        if (axs <= bxe && bxs <= axe) uf_union(abase + i, bbase + j);
        if (axe < bxe) i++; else j++;
    }
}

// ---------------- pass 4: fold run bboxes into final roots ----------------
__global__ void __launch_bounds__(256) k_fold() {
    int wid = threadIdx.x >> 5, lane = threadIdx.x & 31;
    int y = blockIdx.x * 8 + wid;
    int cnt = g_runcnt[y];
    for (int k = lane; k < cnt; k += 32) {
        int sid = y * CAP + k;
        int f = uf_find(sid);
        if (f == sid) continue;
        atomicMin(&g_rxmin[f], g_rxmin[sid]);
        atomicMax(&g_rxmax[f], g_rxmax[sid]);
        atomicMax(&g_rymax[f], g_rymax[sid]);
        if (g_rtext[sid]) atomicMax(&g_rtext[f], 1);
    }
}

// ---------------- output (float32) ----------------
__global__ void k_zero4(float* __restrict__ out, int n4) {
    int i = blockIdx.x * blockDim.x + threadIdx.x;
    if (i < n4) ((float4*)out)[i] = make_float4(0.f, 0.f, 0.f, 0.f);
}
__global__ void k_zero1(float* __restrict__ out, int base, int n) {
    int i = blockIdx.x * blockDim.x + threadIdx.x;
    if (i < n) out[base + i] = 0.f;
}

__global__ void __launch_bounds__(256) k_out(float* __restrict__ out) {
    int wid = threadIdx.x >> 5, lane = threadIdx.x & 31;
    int y = blockIdx.x * 8 + wid;
    int cnt = g_runcnt[y];
    for (int k = lane; k < cnt; k += 32) {
        int sid = y * CAP + k;
        if (__ldcg(&g_rpar[sid]) != sid) continue;   // component root run
        int xs = g_rxs[sid];
        int flat = y * WW + xs;                      // = component min flat index
        int h = g_rymax[sid] - y;
        int w = g_rxmax[sid] - g_rxmin[sid];
        if (h > 4 && w > 4 && g_rtext[sid]) {
            ((float4*)out)[flat] = make_float4((float)y, (float)g_rxmin[sid],
                                               (float)h, (float)w);
            out[4 * NN + flat] = 1.0f;
        }
    }
}

extern "C" void kernel_launch(void* const* d_in, const int* in_sizes, int n_in,
                              void* d_out, int out_size) {
    const float* x = (const float*)d_in[0];
    float* out = (float*)d_out;

    k_bits<<<NN / 256, 256>>>(x);
    k_runs<<<HH / 8, 256>>>();
    k_link<<<(HH - 1 + 255) / 256, 256>>>();
    k_fold<<<HH / 8, 256>>>();

    int n4 = out_size / 4;
    if (n4 > 0) k_zero4<<<(n4 + 255) / 256, 256>>>(out, n4);
    int rem = out_size - n4 * 4;
    if (rem > 0) k_zero1<<<1, 256>>>(out, n4 * 4, rem);

    k_out<<<HH / 8, 256>>>(out);
}